// round 13
// baseline (speedup 1.0000x reference)
#include <cuda_runtime.h>
#include <cuda_bf16.h>

#define Bn 16
#define Sn 512
#define Tn 16
#define Pn 4
#define Gn 128                 // Sn / Pn
#define NPATCH (Bn * Gn * Gn)  // 262144

// Intermediate normalized CAM, layout [b, gy, gx, t] (t contiguous) — 16 MB scratch.
__device__ float g_top[(size_t)NPATCH * Tn];

// ---------------------------------------------------------------------------
// Kernel 1: per-patch c[t] = sum_k input[b, gy*4+py, gx*4+px, t] * W[n, k, 0]
// then (c - min_t) / (max_t - min_t). 16 threads per patch (one per t).
// Streaming loads (__ldcs): input and W are read-once, keep L2 for g_top.
// Normalization via reciprocal+FMUL instead of per-thread FDIV.
// ---------------------------------------------------------------------------
__global__ void __launch_bounds__(256)
patch_cam_kernel(const float* __restrict__ input, const float* __restrict__ w3)
{
    int tid = blockIdx.x * blockDim.x + threadIdx.x;
    int t = tid & 15;
    int n = tid >> 4;                 // patch index: ((b*G)+gy)*G + gx
    int gx = n & (Gn - 1);
    int gy = (n >> 7) & (Gn - 1);
    int b  = n >> 14;

    // Thread t loads W[n, k=t, m=0] (stride 6 floats); broadcast via shfl below.
    float w = __ldcs(&w3[(size_t)n * (Pn * Pn * 6) + t * 6]);

    const float* base = input + (((size_t)b * Sn + gy * Pn) * Sn + gx * Pn) * Tn + t;

    int lane = threadIdx.x & 31;
    unsigned grp = (unsigned)(lane & 16);   // which 16-lane half of the warp

    float acc = 0.0f;
    #pragma unroll
    for (int k = 0; k < 16; ++k) {
        float wk = __shfl_sync(0xffffffffu, w, (int)(grp | (unsigned)k));
        int py = k >> 2;
        int px = k & 3;
        acc = fmaf(__ldcs(&base[((size_t)py * Sn + px) * Tn]), wk, acc);
    }

    // min / max over the 16 t-lanes of this patch (xor 8,4,2,1 stays in-group)
    float mn = acc, mx = acc;
    #pragma unroll
    for (int o = 8; o >= 1; o >>= 1) {
        mn = fminf(mn, __shfl_xor_sync(0xffffffffu, mn, o));
        mx = fmaxf(mx, __shfl_xor_sync(0xffffffffu, mx, o));
    }

    float inv = __frcp_rn(mx - mn);          // MUFU.RCP + Newton, no FDIV chain
    g_top[(size_t)n * Tn + t] = (acc - mn) * inv;
}

// ---------------------------------------------------------------------------
// Kernel 2: bilinear upsample (g,g)->(s,s), align_corners=True.
// R6/R9 champion shape: block = (b, 4 rows) x 512 width, 256 threads.
// Stage 1: y-pre-blend needed g_top rows into smem [4][128][16]
//          (padded to 20 floats/col), unrolled for MLP.
// Stage 2: float4-linear mapping over the output tile: fully coalesced STG,
//          unroll 8 (measured optimum).
// ---------------------------------------------------------------------------
#define COLPAD 20   // floats per padded column (80 B, 16B-aligned)

__global__ void __launch_bounds__(256)
upsample_kernel(float* __restrict__ out)
{
    __shared__ float s[4 * Gn * COLPAD];     // 40960 B: y-blended rows

    int blk = blockIdx.x;
    int yt = blk & (Gn - 1);                 // y-tile (4 rows each)
    int b  = blk >> 7;
    int y0 = yt << 2;

    const float r = 127.0f / 511.0f;

    // Stage 1: 4 rows x 128 cols x 4 float4 = 2048 items, 8 per thread (unrolled).
    #pragma unroll
    for (int it = 0; it < 8; ++it) {
        int i = threadIdx.x + (it << 8);
        int row = i >> 9;                    // 0..3 local y
        int rem = i & 511;
        int col = rem >> 2;
        int q   = rem & 3;

        int y = y0 + row;
        float cy = (float)y * r;
        int i0 = min((int)cy, Gn - 2);
        float wy = cy - (float)i0;

        const float4* g0 = (const float4*)&g_top[(((size_t)(b * Gn + i0))     * Gn + col) * Tn];
        const float4* g1 = (const float4*)&g_top[(((size_t)(b * Gn + i0 + 1)) * Gn + col) * Tn];
        float4 a = g0[q], c = g1[q];
        float4 v;
        v.x = a.x + wy * (c.x - a.x);
        v.y = a.y + wy * (c.y - a.y);
        v.z = a.z + wy * (c.z - a.z);
        v.w = a.w + wy * (c.w - a.w);
        *(float4*)&s[(row * Gn + col) * COLPAD + q * 4] = v;
    }
    __syncthreads();

    // Stage 2: block tile = 4 rows x 512 px x 4 quarters = 8192 float4.
    float4* o4 = (float4*)(out + ((size_t)(b * Sn + y0)) * Sn * Tn);

    #pragma unroll 8
    for (int it = 0; it < 32; ++it) {
        int f = threadIdx.x + (it << 8);     // 0..8191
        int q   = f & 3;
        int x   = (f >> 2) & (Sn - 1);
        int row = f >> 11;

        float cx = (float)x * r;
        int j0 = min((int)cx, Gn - 2);
        float wx = cx - (float)j0;

        const float* sp = &s[(row * Gn + j0) * COLPAD + q * 4];
        float4 a  = *(const float4*)sp;
        float4 bb = *(const float4*)(sp + COLPAD);
        float4 v;
        v.x = a.x + wx * (bb.x - a.x);
        v.y = a.y + wx * (bb.y - a.y);
        v.z = a.z + wx * (bb.z - a.z);
        v.w = a.w + wx * (bb.w - a.w);
        o4[f] = v;
    }
}

extern "C" void kernel_launch(void* const* d_in, const int* in_sizes, int n_in,
                              void* d_out, int out_size)
{
    const float* input = (const float*)d_in[0];   // (16,512,512,16) f32
    const float* w3    = (const float*)d_in[1];   // (262144,16,6)  f32
    float* out = (float*)d_out;                   // (16*512*512, 16) f32

    // Kernel 1: NPATCH * 16 threads (16 threads per patch)
    {
        int total = NPATCH * Tn;                  // 4,194,304
        patch_cam_kernel<<<total / 256, 256>>>(input, w3);
    }
    // Kernel 2: 16 b x 128 y-tiles, 256 threads
    {
        upsample_kernel<<<Bn * Gn, 256>>>(out);
    }
    (void)in_sizes; (void)n_in; (void)out_size;
}

// round 14
// speedup vs baseline: 1.0024x; 1.0024x over previous
#include <cuda_runtime.h>
#include <cuda_bf16.h>

#define Bn 16
#define Sn 512
#define Tn 16
#define Pn 4
#define Gn 128                 // Sn / Pn
#define NPATCH (Bn * Gn * Gn)  // 262144

// Intermediate normalized CAM, layout [b, gy, gx, t] (t contiguous) — 16 MB scratch.
__device__ float g_top[(size_t)NPATCH * Tn];

// ---------------------------------------------------------------------------
// Kernel 1: per-patch c[t] = sum_k input[b, gy*4+py, gx*4+px, t] * W[n, k, 0]
// then (c - min_t) / (max_t - min_t). 16 threads per patch (one per t).
// Streaming loads (__ldcs): input and W are read-once, keep L2 for g_top.
// ---------------------------------------------------------------------------
__global__ void __launch_bounds__(256)
patch_cam_kernel(const float* __restrict__ input, const float* __restrict__ w3)
{
    int tid = blockIdx.x * blockDim.x + threadIdx.x;
    int t = tid & 15;
    int n = tid >> 4;                 // patch index: ((b*G)+gy)*G + gx
    int gx = n & (Gn - 1);
    int gy = (n >> 7) & (Gn - 1);
    int b  = n >> 14;

    // Thread t loads W[n, k=t, m=0] (stride 6 floats); broadcast via shfl below.
    float w = __ldcs(&w3[(size_t)n * (Pn * Pn * 6) + t * 6]);

    const float* base = input + (((size_t)b * Sn + gy * Pn) * Sn + gx * Pn) * Tn + t;

    int lane = threadIdx.x & 31;
    unsigned grp = (unsigned)(lane & 16);   // which 16-lane half of the warp

    float acc = 0.0f;
    #pragma unroll
    for (int k = 0; k < 16; ++k) {
        float wk = __shfl_sync(0xffffffffu, w, (int)(grp | (unsigned)k));
        int py = k >> 2;
        int px = k & 3;
        acc = fmaf(__ldcs(&base[((size_t)py * Sn + px) * Tn]), wk, acc);
    }

    // min / max over the 16 t-lanes of this patch (xor 8,4,2,1 stays in-group)
    float mn = acc, mx = acc;
    #pragma unroll
    for (int o = 8; o >= 1; o >>= 1) {
        mn = fminf(mn, __shfl_xor_sync(0xffffffffu, mn, o));
        mx = fmaxf(mx, __shfl_xor_sync(0xffffffffu, mx, o));
    }

    g_top[(size_t)n * Tn + t] = (acc - mn) / (mx - mn);
}

// ---------------------------------------------------------------------------
// Kernel 2: bilinear upsample (g,g)->(s,s), align_corners=True.
// R6/R9 champion shape: block = (b, 4 rows) x 512 width, 256 threads.
// Stage 1: y-pre-blend needed g_top rows into smem [4][128][16]
//          (padded to 20 floats/col), unrolled for MLP.
// Stage 2: float4-linear mapping over the output tile: fully coalesced STG,
//          unroll 8 (measured optimum).
// ---------------------------------------------------------------------------
#define COLPAD 20   // floats per padded column (80 B, 16B-aligned)

__global__ void __launch_bounds__(256)
upsample_kernel(float* __restrict__ out)
{
    __shared__ float s[4 * Gn * COLPAD];     // 40960 B: y-blended rows

    int blk = blockIdx.x;
    int yt = blk & (Gn - 1);                 // y-tile (4 rows each)
    int b  = blk >> 7;
    int y0 = yt << 2;

    const float r = 127.0f / 511.0f;

    // Stage 1: 4 rows x 128 cols x 4 float4 = 2048 items, 8 per thread (unrolled).
    #pragma unroll
    for (int it = 0; it < 8; ++it) {
        int i = threadIdx.x + (it << 8);
        int row = i >> 9;                    // 0..3 local y
        int rem = i & 511;
        int col = rem >> 2;
        int q   = rem & 3;

        int y = y0 + row;
        float cy = (float)y * r;
        int i0 = min((int)cy, Gn - 2);
        float wy = cy - (float)i0;

        const float4* g0 = (const float4*)&g_top[(((size_t)(b * Gn + i0))     * Gn + col) * Tn];
        const float4* g1 = (const float4*)&g_top[(((size_t)(b * Gn + i0 + 1)) * Gn + col) * Tn];
        float4 a = g0[q], c = g1[q];
        float4 v;
        v.x = a.x + wy * (c.x - a.x);
        v.y = a.y + wy * (c.y - a.y);
        v.z = a.z + wy * (c.z - a.z);
        v.w = a.w + wy * (c.w - a.w);
        *(float4*)&s[(row * Gn + col) * COLPAD + q * 4] = v;
    }
    __syncthreads();

    // Stage 2: block tile = 4 rows x 512 px x 4 quarters = 8192 float4.
    float4* o4 = (float4*)(out + ((size_t)(b * Sn + y0)) * Sn * Tn);

    #pragma unroll 8
    for (int it = 0; it < 32; ++it) {
        int f = threadIdx.x + (it << 8);     // 0..8191
        int q   = f & 3;
        int x   = (f >> 2) & (Sn - 1);
        int row = f >> 11;

        float cx = (float)x * r;
        int j0 = min((int)cx, Gn - 2);
        float wx = cx - (float)j0;

        const float* sp = &s[(row * Gn + j0) * COLPAD + q * 4];
        float4 a  = *(const float4*)sp;
        float4 bb = *(const float4*)(sp + COLPAD);
        float4 v;
        v.x = a.x + wx * (bb.x - a.x);
        v.y = a.y + wx * (bb.y - a.y);
        v.z = a.z + wx * (bb.z - a.z);
        v.w = a.w + wx * (bb.w - a.w);
        o4[f] = v;
    }
}

extern "C" void kernel_launch(void* const* d_in, const int* in_sizes, int n_in,
                              void* d_out, int out_size)
{
    const float* input = (const float*)d_in[0];   // (16,512,512,16) f32
    const float* w3    = (const float*)d_in[1];   // (262144,16,6)  f32
    float* out = (float*)d_out;                   // (16*512*512, 16) f32

    // Kernel 1: NPATCH * 16 threads (16 threads per patch)
    {
        int total = NPATCH * Tn;                  // 4,194,304
        patch_cam_kernel<<<total / 256, 256>>>(input, w3);
    }
    // Kernel 2: 16 b x 128 y-tiles, 256 threads
    {
        upsample_kernel<<<Bn * Gn, 256>>>(out);
    }
    (void)in_sizes; (void)n_in; (void)out_size;
}